// round 2
// baseline (speedup 1.0000x reference)
#include <cuda_runtime.h>
#include <cstdint>

#define NNODES 50000
#define NEDGES 800000
#define HID 64

// ---------------- scratch (static device globals; no allocation) ----------------
__device__ float    g_h[NNODES * HID];
__device__ float    g_s[NNODES];
__device__ float    g_d[NNODES];
__device__ unsigned g_menc[NNODES];
__device__ float    g_den[NNODES];
__device__ float    g_agg[NNODES * HID];
__device__ float    g_y0[NNODES * HID];
__device__ float    g_y1[NNODES * HID];
__device__ float    g_y4[NNODES * HID];
__device__ float    g_logit[NEDGES];
__device__ float    g_bufA[(size_t)NEDGES * 128];
__device__ float    g_bufB[(size_t)NEDGES * 128];
__device__ float    g_we[4];

// ---------------- helpers ----------------
__device__ __forceinline__ unsigned ord_enc(float f) {
    unsigned u = __float_as_uint(f);
    return (u & 0x80000000u) ? ~u : (u | 0x80000000u);
}
__device__ __forceinline__ float ord_dec(unsigned u) {
    return (u & 0x80000000u) ? __uint_as_float(u ^ 0x80000000u) : __uint_as_float(~u);
}

// ---------------- tiny prep: w = We @ ae for both GAT layers ----------------
__global__ void k_prep_we(const float* __restrict__ We1, const float* __restrict__ ae1,
                          const float* __restrict__ We2, const float* __restrict__ ae2) {
    int t = threadIdx.x;
    if (t < 4) {
        const float* W = (t < 2) ? We1 : We2;
        const float* a = (t < 2) ? ae1 : ae2;
        int r = t & 1;
        float s = 0.f;
        for (int j = 0; j < HID; j++) s += W[r * HID + j] * a[j];
        g_we[t] = s;
    }
}

// ---------------- per-call re-init of aggregation scratch ----------------
__global__ void k_init() {
    int gid = blockIdx.x * blockDim.x + threadIdx.x;
    if (gid < NNODES * HID) g_agg[gid] = 0.f;
    if (gid < NNODES) { g_den[gid] = 0.f; g_menc[gid] = 0x007fffffu; /* enc(-inf) */ }
}

// ---------------- node GEMM: H = X @ W (MODE0: +scores; MODE1: relu(X1+X2 gemm + bias)) ----
template <int K, int MODE>
__global__ __launch_bounds__(128) void k_node_gemm(
    const float* __restrict__ X, const float* __restrict__ X2,
    const float* __restrict__ W, const float* __restrict__ v1,
    const float* __restrict__ v2,
    float* __restrict__ H, float* __restrict__ S, float* __restrict__ D) {
    __shared__ float Ws[K * HID];
    __shared__ float sv1[HID], sv2[HID];
    int tid = threadIdx.x;
    for (int i = tid; i < K * HID; i += 128) Ws[i] = W[i];
    if (tid < HID) {
        sv1[tid] = v1 ? v1[tid] : 0.f;
        sv2[tid] = v2 ? v2[tid] : 0.f;
    }
    __syncthreads();
    int node = blockIdx.x * 128 + tid;
    if (node >= NNODES) return;

    float acc[HID];
#pragma unroll
    for (int n = 0; n < HID; n++) acc[n] = 0.f;

    const float4* xr = reinterpret_cast<const float4*>(X + (size_t)node * K);
    const float4* xr2 = (MODE == 1) ? reinterpret_cast<const float4*>(X2 + (size_t)node * K) : nullptr;
#pragma unroll 1
    for (int k4 = 0; k4 < K / 4; k4++) {
        float4 v = __ldg(xr + k4);
        if (MODE == 1) {
            float4 w = __ldg(xr2 + k4);
            v.x += w.x; v.y += w.y; v.z += w.z; v.w += w.w;
        }
        float xv[4] = {v.x, v.y, v.z, v.w};
#pragma unroll
        for (int kk = 0; kk < 4; kk++) {
            const float* wr = &Ws[(k4 * 4 + kk) * HID];
#pragma unroll
            for (int n = 0; n < HID; n++) acc[n] = fmaf(xv[kk], wr[n], acc[n]);
        }
    }

    if (MODE == 0) {
        float s = 0.f, d = 0.f;
#pragma unroll
        for (int n = 0; n < HID; n++) { s += acc[n] * sv1[n]; d += acc[n] * sv2[n]; }
        S[node] = s;
        D[node] = d;
    } else {
#pragma unroll
        for (int n = 0; n < HID; n++) acc[n] = fmaxf(acc[n] + sv1[n], 0.f);
    }
    float4* hr = reinterpret_cast<float4*>(H + (size_t)node * HID);
#pragma unroll
    for (int i = 0; i < HID / 4; i++)
        hr[i] = make_float4(acc[4 * i], acc[4 * i + 1], acc[4 * i + 2], acc[4 * i + 3]);
}

// ---------------- edge logit + segment max ----------------
__global__ void k_edge_logit(const int* __restrict__ EI, const float* __restrict__ EA, int which) {
    int e = blockIdx.x * blockDim.x + threadIdx.x;
    if (e >= NEDGES) return;
    int src = __ldg(EI + e);
    int dst = __ldg(EI + NEDGES + e);
    float w0 = g_we[which * 2], w1 = g_we[which * 2 + 1];
    float lg = __ldg(&g_s[src]) + __ldg(&g_d[dst]) + __ldg(EA + 2 * e) * w0 + __ldg(EA + 2 * e + 1) * w1;
    lg = (lg > 0.f) ? lg : 0.2f * lg;  // leaky_relu, slope 0.2
    g_logit[e] = lg;
    atomicMax(&g_menc[dst], ord_enc(lg));
}

// ---------------- edge exp + den + unnormalized aggregation ----------------
__global__ void k_edge_exp_agg(const int* __restrict__ EI) {
    long long gid = (long long)blockIdx.x * blockDim.x + threadIdx.x;
    int e = (int)(gid >> 6);
    int n = (int)(gid & 63);
    if (e >= NEDGES) return;
    int src = __ldg(EI + e);
    int dst = __ldg(EI + NEDGES + e);
    float m = ord_dec(g_menc[dst]);
    float ex = expf(g_logit[e] - m);
    float val = ex * __ldg(&g_h[(size_t)src * HID + n]);
    atomicAdd(&g_agg[(size_t)dst * HID + n], val);
    if (n == 0) atomicAdd(&g_den[dst], ex);
}

// ---------------- normalize + bias + relu ----------------
__global__ void k_node_fin(const float* __restrict__ bias, float* __restrict__ Y) {
    int gid = blockIdx.x * blockDim.x + threadIdx.x;
    if (gid >= NNODES * HID) return;
    int n = gid & 63;
    float den = fmaxf(g_den[gid >> 6], 1e-16f);
    Y[gid] = fmaxf(g_agg[gid] / den + __ldg(bias + n), 0.f);
}

// ---------------- build concat([y4[src]+y4[dst], relu(ea@We0+be0)]) ----------------
__global__ __launch_bounds__(128) void k_build_xb(
    const int* __restrict__ EI, const float* __restrict__ EA,
    const float* __restrict__ We0, const float* __restrict__ be0,
    const float* __restrict__ Y4, float* __restrict__ XB) {
    int e = blockIdx.x;
    int c = threadIdx.x;
    int src = __ldg(EI + e);
    int dst = __ldg(EI + NEDGES + e);
    float v;
    if (c < HID) {
        v = __ldg(&Y4[(size_t)src * HID + c]) + __ldg(&Y4[(size_t)dst * HID + c]);
    } else {
        int c2 = c - HID;
        v = fmaxf(__ldg(EA + 2 * e) * __ldg(We0 + c2) + __ldg(EA + 2 * e + 1) * __ldg(We0 + HID + c2)
                      + __ldg(be0 + c2),
                  0.f);
    }
    XB[(size_t)e * 128 + c] = v;
}

// ---------------- register-tiled SGEMM: C = act(A @ B + bias) ----------------
template <int BM, int BN, int BK, int TM, int TN, bool RELU>
__global__ __launch_bounds__((BM / TM) * (BN / TN)) void k_gemm(
    const float* __restrict__ A, const float* __restrict__ B,
    const float* __restrict__ bias, float* __restrict__ C,
    int M, int N, int K) {
    constexpr int TX = BN / TN;
    constexpr int TY = BM / TM;
    constexpr int NT = TX * TY;
    __shared__ float As[BK][BM];
    __shared__ float Bs[BK][BN];

    int tid = threadIdx.x;
    int tx = tid % TX, ty = tid / TX;
    int m0 = blockIdx.x * BM;
    int n0 = blockIdx.y * BN;

    float acc[TM][TN];
#pragma unroll
    for (int i = 0; i < TM; i++)
#pragma unroll
        for (int j = 0; j < TN; j++) acc[i][j] = 0.f;

    for (int kb = 0; kb < K; kb += BK) {
        // A tile (M multiple of BM, K multiple of BK)
#pragma unroll
        for (int i = tid; i < BM * BK / 4; i += NT) {
            int row = i / (BK / 4);
            int kc = (i % (BK / 4)) * 4;
            float4 v = *reinterpret_cast<const float4*>(A + (size_t)(m0 + row) * K + kb + kc);
            As[kc + 0][row] = v.x;
            As[kc + 1][row] = v.y;
            As[kc + 2][row] = v.z;
            As[kc + 3][row] = v.w;
        }
        // B tile (guard columns for N not multiple of BN)
#pragma unroll
        for (int i = tid; i < BK * BN; i += NT) {
            int row = i / BN;
            int c = i % BN;
            int gc = n0 + c;
            Bs[row][c] = (gc < N) ? __ldg(B + (size_t)(kb + row) * N + gc) : 0.f;
        }
        __syncthreads();
#pragma unroll
        for (int k = 0; k < BK; k++) {
            float a[TM], b[TN];
            if constexpr (TM % 4 == 0) {
                const float4* ap = reinterpret_cast<const float4*>(&As[k][ty * TM]);
#pragma unroll
                for (int i = 0; i < TM / 4; i++) {
                    float4 v = ap[i];
                    a[4 * i] = v.x; a[4 * i + 1] = v.y; a[4 * i + 2] = v.z; a[4 * i + 3] = v.w;
                }
            } else {
#pragma unroll
                for (int i = 0; i < TM; i++) a[i] = As[k][ty * TM + i];
            }
            if constexpr (TN % 4 == 0) {
                const float4* bp = reinterpret_cast<const float4*>(&Bs[k][tx * TN]);
#pragma unroll
                for (int j = 0; j < TN / 4; j++) {
                    float4 v = bp[j];
                    b[4 * j] = v.x; b[4 * j + 1] = v.y; b[4 * j + 2] = v.z; b[4 * j + 3] = v.w;
                }
            } else {
#pragma unroll
                for (int j = 0; j < TN; j++) b[j] = Bs[k][tx * TN + j];
            }
#pragma unroll
            for (int i = 0; i < TM; i++)
#pragma unroll
                for (int j = 0; j < TN; j++) acc[i][j] = fmaf(a[i], b[j], acc[i][j]);
        }
        __syncthreads();
    }

#pragma unroll
    for (int i = 0; i < TM; i++) {
        size_t gm = (size_t)(m0 + ty * TM + i);
#pragma unroll
        for (int j = 0; j < TN; j++) {
            int gn = n0 + tx * TN + j;
            if (gn < N) {
                float v = acc[i][j] + __ldg(bias + gn);
                if (RELU) v = fmaxf(v, 0.f);
                C[gm * N + gn] = v;
            }
        }
    }
}

// ---------------- launch ----------------
extern "C" void kernel_launch(void* const* d_in, const int* in_sizes, int n_in,
                              void* d_out, int out_size) {
    const float* x   = (const float*)d_in[0];
    const int*   ei  = (const int*)d_in[1];
    const float* ea  = (const float*)d_in[2];
    const float* Wg1 = (const float*)d_in[4];
    const float* as1 = (const float*)d_in[5];
    const float* ad1 = (const float*)d_in[6];
    const float* We1 = (const float*)d_in[7];
    const float* ae1 = (const float*)d_in[8];
    const float* bg1 = (const float*)d_in[9];
    const float* Wg2 = (const float*)d_in[10];
    const float* as2 = (const float*)d_in[11];
    const float* ad2 = (const float*)d_in[12];
    const float* We2 = (const float*)d_in[13];
    const float* ae2 = (const float*)d_in[14];
    const float* bg2 = (const float*)d_in[15];
    const float* W2  = (const float*)d_in[16];
    const float* b2  = (const float*)d_in[17];
    const float* We0 = (const float*)d_in[18];
    const float* be0 = (const float*)d_in[19];
    const float* W3  = (const float*)d_in[20];
    const float* b3  = (const float*)d_in[21];
    const float* Wm0 = (const float*)d_in[22];
    const float* bm0 = (const float*)d_in[23];
    const float* Wm1 = (const float*)d_in[24];
    const float* bm1 = (const float*)d_in[25];
    const float* Wm2 = (const float*)d_in[26];
    const float* bm2 = (const float*)d_in[27];
    const float* W4  = (const float*)d_in[28];
    const float* b4  = (const float*)d_in[29];
    float* out = (float*)d_out;

    float *p_h, *p_s, *p_d, *p_y0, *p_y1, *p_y4, *p_A, *p_B;
    cudaGetSymbolAddress((void**)&p_h, g_h);
    cudaGetSymbolAddress((void**)&p_s, g_s);
    cudaGetSymbolAddress((void**)&p_d, g_d);
    cudaGetSymbolAddress((void**)&p_y0, g_y0);
    cudaGetSymbolAddress((void**)&p_y1, g_y1);
    cudaGetSymbolAddress((void**)&p_y4, g_y4);
    cudaGetSymbolAddress((void**)&p_A, g_bufA);
    cudaGetSymbolAddress((void**)&p_B, g_bufB);

    const int initGrid = (NNODES * HID + 255) / 256;
    const int nodeGrid = (NNODES + 127) / 128;
    const int edgeGrid = (NEDGES + 255) / 256;
    const int aggGrid  = (int)(((long long)NEDGES * HID) / 256);

    k_prep_we<<<1, 32>>>(We1, ae1, We2, ae2);

    // ---- GAT layer 1 ----
    k_init<<<initGrid, 256>>>();
    k_node_gemm<128, 0><<<nodeGrid, 128>>>(x, nullptr, Wg1, as1, ad1, p_h, p_s, p_d);
    k_edge_logit<<<edgeGrid, 256>>>(ei, ea, 0);
    k_edge_exp_agg<<<aggGrid, 256>>>(ei);
    k_node_fin<<<initGrid, 256>>>(bg1, p_y0);

    // ---- GAT layer 2 ----
    k_init<<<initGrid, 256>>>();
    k_node_gemm<64, 0><<<nodeGrid, 128>>>(p_y0, nullptr, Wg2, as2, ad2, p_h, p_s, p_d);
    k_edge_logit<<<edgeGrid, 256>>>(ei, ea, 1);
    k_edge_exp_agg<<<aggGrid, 256>>>(ei);
    k_node_fin<<<initGrid, 256>>>(bg2, p_y1);

    // ---- l2: y4 = relu((y0+y1) @ W2 + b2) ----
    k_node_gemm<64, 1><<<nodeGrid, 128>>>(p_y0, p_y1, W2, b2, nullptr, p_y4, nullptr, nullptr);

    // ---- edge MLP ----
    k_build_xb<<<NEDGES, 128>>>(ei, ea, We0, be0, p_y4, p_A);

    dim3 gh(NEDGES / 128, 1);
    k_gemm<128, 128, 16, 8, 8, true><<<gh, 256>>>(p_A, W3, b3, p_B, NEDGES, 128, 128);
    k_gemm<128, 128, 16, 8, 8, true><<<gh, 256>>>(p_B, Wm0, bm0, p_A, NEDGES, 128, 128);
    k_gemm<128, 128, 16, 8, 8, true><<<gh, 256>>>(p_A, Wm1, bm1, p_B, NEDGES, 128, 128);
    k_gemm<128, 128, 16, 8, 8, true><<<gh, 256>>>(p_B, Wm2, bm2, p_A, NEDGES, 128, 128);

    dim3 gf(NEDGES / 128, 2);  // BN=80 covers 145 output cols in 2 column blocks
    k_gemm<128, 80, 16, 8, 5, false><<<gf, 256>>>(p_A, W4, b4, out, NEDGES, 145, 128);
}